// round 13
// baseline (speedup 1.0000x reference)
#include <cuda_runtime.h>
#include <cuda_fp16.h>
#include <cstdint>
#include <math.h>

// ---------------- problem constants ----------------
#define BATCH 8
#define CIN   64
#define COUT  64
#define SDIM  512
#define HH    256
#define WW    256
#define TAPS  9

#define CONV_SCALE (1.0f / 24.0f)
#define MOD_SCALE  (0.04419417382415922f)
#define EPSV       (1e-8f)

// ---------------- helpers ----------------
__device__ __forceinline__ uint32_t smem_u32(const void* p) {
    uint32_t a;
    asm("{ .reg .u64 t; cvta.to.shared.u64 t, %1; cvt.u32.u64 %0, t; }" : "=r"(a) : "l"(p));
    return a;
}
__device__ __forceinline__ void ldsm4(uint32_t (&r)[4], uint32_t addr) {
    asm volatile("ldmatrix.sync.aligned.m8n8.x4.shared.b16 {%0,%1,%2,%3}, [%4];"
                 : "=r"(r[0]), "=r"(r[1]), "=r"(r[2]), "=r"(r[3]) : "r"(addr));
}
__device__ __forceinline__ void mma16816(float (&c)[4], const uint32_t (&a)[4],
                                         const uint32_t b0, const uint32_t b1) {
    asm volatile(
        "mma.sync.aligned.m16n8k16.row.col.f32.f16.f16.f32 "
        "{%0,%1,%2,%3}, {%4,%5,%6,%7}, {%8,%9}, {%0,%1,%2,%3};"
        : "+f"(c[0]), "+f"(c[1]), "+f"(c[2]), "+f"(c[3])
        : "r"(a[0]), "r"(a[1]), "r"(a[2]), "r"(a[3]), "r"(b0), "r"(b1));
}
__device__ __forceinline__ void cpasync16(uint32_t dst, const void* src) {
    asm volatile("cp.async.cg.shared.global [%0], [%1], 16;" :: "r"(dst), "l"(src) : "memory");
}
__device__ __forceinline__ void cpcommit() { asm volatile("cp.async.commit_group;" ::: "memory"); }
__device__ __forceinline__ void cpwait0()  { asm volatile("cp.async.wait_group 0;" ::: "memory"); }

__device__ __forceinline__ uint32_t sw128(uint32_t o) { return o ^ ((o >> 3) & 0x70u); }

// ---------------- single persistent kernel ---------------------------------
// Work unit = chunk (xh, y4chunk, b): 128px x 64co x 4 rows (2 pairs).
// 8 warps (256 thr): 4 in M (32px) x 2 in N (32co), rows paired,
// register-double-buffered fragments (R11 core).
// Demodulated fp16 weights are computed IN-KERNEL per CTA (per distinct b)
// directly into the SMEM W region — no demod kernel, no global W roundtrip.
#define W_OFF      0u
#define W_BYTES    73728u
#define RING_OFF   73728u
#define ROW_STRIDE 16640u                        // 130 px x 128B
#define STAGE_OFF  (RING_OFF + 6u * ROW_STRIDE)  // 173568
#define STAGE_W    136                           // fp32 words per ci row
#define SMEM_TOTAL (STAGE_OFF + 64u * STAGE_W * 4u)   // 208384

#define NCTA       148

__global__ __launch_bounds__(256, 1)
void conv_kernel(const float* __restrict__ in,
                 const float* __restrict__ style,
                 const float* __restrict__ mw,
                 const float* __restrict__ mbias,
                 const float* __restrict__ wgt,
                 float* __restrict__ out) {
    extern __shared__ char smem[];
    const uint32_t sb = smem_u32(smem);
    const int tid  = threadIdx.x;
    const int wid  = tid >> 5;
    const int lane = tid & 31;

    const int mwarp = wid & 3;
    const int nwarp = wid >> 2;
    const uint32_t px0 = mwarp * 32;
    const uint32_t co0 = nwarp * 32;

    const uint32_t arow = lane & 15;
    const uint32_t khA  = ((lane >> 4) & 1) * 16;
    const uint32_t brow = (lane & 7) | ((lane >> 1) & 8);
    const uint32_t khB  = ((lane >> 3) & 1) * 16;

    // chunk range: 136 CTAs x 7, 12 CTAs x 6  (1024 = 136*7 + 12*6)
    const int cta = blockIdx.x;
    int c, cnt;
    if (cta < 136) { c = cta * 7;               cnt = 7; }
    else           { c = 952 + (cta - 136) * 6; cnt = 6; }

    float* sOut = (float*)(smem + STAGE_OFF);    // [64co][132px] f32 (reuses stage)
    const int eg = lane >> 2;
    const int et = lane & 3;

    // ---- in-CTA demodulated weight computation for batch bb ----
    auto compute_weights = [&](int bb) {
        float* sdot = (float*)(smem + STAGE_OFF);   // scratch (stage unused yet)
        // phase 1: sdot[ci] = MOD_SCALE * <style_bb, mw_ci> + mbias[ci]
        {
            int ci = tid >> 2, qq = tid & 3;
            const float4* sp = (const float4*)(style + (size_t)bb * SDIM) + qq * 32;
            const float4* wp = (const float4*)(mw + (size_t)ci * SDIM) + qq * 32;
            float sum = 0.f;
            #pragma unroll 8
            for (int it = 0; it < 32; it++) {
                float4 s4 = sp[it];
                float4 w4 = wp[it];
                sum += s4.x * w4.x + s4.y * w4.y + s4.z * w4.z + s4.w * w4.w;
            }
            sum += __shfl_xor_sync(0xFFFFFFFFu, sum, 1);
            sum += __shfl_xor_sync(0xFFFFFFFFu, sum, 2);
            if (qq == 0) sdot[ci] = sum * MOD_SCALE + mbias[ci];
        }
        __syncthreads();
        // phase 2: warp w owns co = 8w..8w+7; lane sums 18 of 576 elements
        #pragma unroll 1
        for (int i = 0; i < 8; i++) {
            int co = wid * 8 + i;
            const float* wrow = wgt + (size_t)co * 576;
            float val[18];
            float sumsq = 0.f;
            #pragma unroll
            for (int k = 0; k < 18; k++) {
                int e  = lane + 32 * k;
                int ci = e / 9;
                float v = CONV_SCALE * wrow[e] * sdot[ci];
                val[k] = v;
                sumsq += v * v;
            }
            #pragma unroll
            for (int off = 16; off > 0; off >>= 1)
                sumsq += __shfl_xor_sync(0xFFFFFFFFu, sumsq, off);
            float dm = rsqrtf(sumsq + EPSV);
            #pragma unroll
            for (int k = 0; k < 18; k++) {
                int e   = lane + 32 * k;
                int ci  = e / 9;
                int tap = e - ci * 9;
                uint32_t o = ((uint32_t)(tap * 64 + co)) * 128u + (uint32_t)ci * 2u;
                *(__half*)(smem + W_OFF + sw128(o)) = __float2half_rn(val[k] * dm);
            }
        }
        __syncthreads();
    };

    int last_b = -1;

    while (cnt > 0) {
        const int col    = c >> 6;          // 16 columns = b(8) x xh(2)
        const int within = c & 63;
        const int b  = col >> 1;
        const int x0 = (col & 1) * 128;
        const int run = min(cnt, 64 - within);
        const int y0r = within * 4;
        const int npairs = run * 2;

        // ---- stage one raw fp32 input row into the stage buffer ----
        auto stage_async = [&](int iy) {
            if ((unsigned)iy >= 256u) return;
            #pragma unroll
            for (int it = 0; it < 9; it++) {
                int idx = tid + 256 * it;        // 64 ci x 34 chunks = 2176
                if (idx < 2176) {
                    int ci = idx / 34;
                    int cc = idx - ci * 34;
                    int gx0 = x0 - 4 + 4 * cc;
                    uint32_t doff = STAGE_OFF + (uint32_t)(ci * STAGE_W + 4 * cc) * 4u;
                    if ((unsigned)gx0 <= 252u) {
                        cpasync16(sb + doff,
                                  in + (((size_t)(b * CIN + ci)) * HH + iy) * WW + gx0);
                    } else {
                        *(uint4*)(smem + doff) = make_uint4(0, 0, 0, 0);
                    }
                }
            }
        };

        // ---- convert staged fp32 row -> swizzled fp16 ring slot ----
        auto convert_row = [&](int iy) {
            const uint32_t roff = RING_OFF
                + ((uint32_t)((iy + 1 + 768) % 6)) * ROW_STRIDE;
            const bool valid = ((unsigned)iy < 256u);
            const float* st = (const float*)(smem + STAGE_OFF);
            const int g = wid;
            #pragma unroll
            for (int it = 0; it < 5; it++) {
                int px = (it < 4) ? (it * 32 + lane) : (128 + lane);
                if (it == 4 && lane >= 2) break;
                float v[8];
                #pragma unroll
                for (int k = 0; k < 8; k++)
                    v[k] = valid ? st[(g * 8 + k) * STAGE_W + px + 3] : 0.f;
                uint32_t u[4];
                #pragma unroll
                for (int k = 0; k < 4; k++) {
                    __half2 hp = __floats2half2_rn(v[2 * k], v[2 * k + 1]);
                    u[k] = *reinterpret_cast<uint32_t*>(&hp);
                }
                *(uint4*)(smem + roff + sw128((uint32_t)px * 128u + (uint32_t)g * 16u))
                    = make_uint4(u[0], u[1], u[2], u[3]);
            }
        };

        // ---- run prologue: weights (if b changed) + prime rows ----
        if (b != last_b) {
            compute_weights(b);
            last_b = b;
        }
        #pragma unroll 1
        for (int rnd = 0; rnd < 4; rnd++) {
            stage_async(y0r - 1 + rnd);
            cpcommit();
            cpwait0();
            __syncthreads();
            convert_row(y0r - 1 + rnd);
            __syncthreads();
        }

        // ---- continuous pair loop across the whole run ----
        for (int q = 0; q < npairs; q++) {
            const int y = y0r + 2 * q;
            const bool more = (q < npairs - 1);

            if (more) { stage_async(y + 3); cpcommit(); }

            uint32_t rowA[4];
            #pragma unroll
            for (int j = 0; j < 4; j++)
                rowA[j] = sb + RING_OFF + ((uint32_t)((y + j) % 6)) * ROW_STRIDE;

            float acc[2][2][4][4];
            #pragma unroll
            for (int r = 0; r < 2; r++)
                #pragma unroll
                for (int mf = 0; mf < 2; mf++)
                    #pragma unroll
                    for (int nf = 0; nf < 4; nf++)
                        #pragma unroll
                        for (int cc = 0; cc < 4; cc++) acc[r][mf][nf][cc] = 0.f;

            // double-buffered fragments
            uint32_t afr[2][4][2][4];      // [buf][row][mf][4]
            uint32_t wfr[2][3][4][2];      // [buf][dy][nf][2]

            auto prefetch = [&](int s, int buf) {
                const int kc = s / 3;
                const uint32_t dx = (uint32_t)(s - 3 * kc);
                const uint32_t kb = (uint32_t)kc * 32u;
                #pragma unroll
                for (int dy = 0; dy < 3; dy++) {
                    const uint32_t tap = (uint32_t)(dy * 3) + dx;
                    #pragma unroll
                    for (int g = 0; g < 2; g++) {
                        uint32_t tmp[4];
                        uint32_t o = (tap * 64u + co0 + (uint32_t)g * 16u + brow) * 128u
                                     + kb + khB;
                        ldsm4(tmp, sb + W_OFF + sw128(o));
                        wfr[buf][dy][g * 2][0]     = tmp[0];
                        wfr[buf][dy][g * 2][1]     = tmp[1];
                        wfr[buf][dy][g * 2 + 1][0] = tmp[2];
                        wfr[buf][dy][g * 2 + 1][1] = tmp[3];
                    }
                }
                #pragma unroll
                for (int j = 0; j < 4; j++) {
                    #pragma unroll
                    for (int mf = 0; mf < 2; mf++) {
                        uint32_t o = (px0 + (uint32_t)mf * 16u + arow + dx) * 128u
                                     + kb + khA;
                        ldsm4(afr[buf][j][mf], rowA[j] + sw128(o));
                    }
                }
            };

            prefetch(0, 0);
            #pragma unroll
            for (int s = 0; s < 12; s++) {
                const int buf = s & 1;
                if (s < 11) prefetch(s + 1, buf ^ 1);
                #pragma unroll
                for (int dy = 0; dy < 3; dy++)
                    #pragma unroll
                    for (int r = 0; r < 2; r++)
                        #pragma unroll
                        for (int mf = 0; mf < 2; mf++)
                            #pragma unroll
                            for (int nf = 0; nf < 4; nf++)
                                mma16816(acc[r][mf][nf], afr[buf][r + dy][mf],
                                         wfr[buf][dy][nf][0], wfr[buf][dy][nf][1]);
                // mid-pair: consume staged row y+3, start staging row y+4
                if (s == 5 && more) {
                    cpwait0();
                    __syncthreads();
                    convert_row(y + 3);          // -> slot (y+4)%6 (free)
                    __syncthreads();
                    stage_async(y + 4);
                    cpcommit();
                }
            }

            if (more) {
                cpwait0();
                __syncthreads();
                convert_row(y + 4);              // -> slot (y+5)%6 (free)
            }
            __syncthreads();

            // ---- epilogue: two rows via smem transpose (stage reused) ----
            #pragma unroll
            for (int r = 0; r < 2; r++) {
                #pragma unroll
                for (int mf = 0; mf < 2; mf++) {
                    #pragma unroll
                    for (int nf = 0; nf < 4; nf++) {
                        int px = px0 + mf * 16 + eg;
                        int co = co0 + nf * 8 + 2 * et;
                        sOut[co * 132 + px]           = acc[r][mf][nf][0];
                        sOut[(co + 1) * 132 + px]     = acc[r][mf][nf][1];
                        sOut[co * 132 + px + 8]       = acc[r][mf][nf][2];
                        sOut[(co + 1) * 132 + px + 8] = acc[r][mf][nf][3];
                    }
                }
                __syncthreads();
                #pragma unroll
                for (int k = 0; k < 8; k++) {
                    int idx = tid + 256 * k;        // 2048 float4
                    int co = idx >> 5;
                    int qq = idx & 31;
                    float4 v = *(float4*)&sOut[co * 132 + qq * 4];
                    *(float4*)(out + (((size_t)b * COUT + co) * HH + (y + r)) * WW
                               + x0 + qq * 4) = v;
                }
                __syncthreads();
            }
        }

        c   += run;
        cnt -= run;
    }
}

// ---------------- launch ----------------
extern "C" void kernel_launch(void* const* d_in, const int* in_sizes, int n_in,
                              void* d_out, int out_size) {
    const float* input      = (const float*)d_in[0];
    const float* style      = (const float*)d_in[1];
    const float* weight     = (const float*)d_in[2];
    const float* mod_weight = (const float*)d_in[3];
    const float* mod_bias   = (const float*)d_in[4];
    float* out = (float*)d_out;

    cudaFuncSetAttribute(conv_kernel,
                         cudaFuncAttributeMaxDynamicSharedMemorySize, SMEM_TOTAL);

    conv_kernel<<<NCTA, 256, SMEM_TOTAL>>>(input, style, mod_weight, mod_bias,
                                           weight, out);
}